// round 9
// baseline (speedup 1.0000x reference)
#include <cuda_runtime.h>
#include <math.h>

// Problem constants (fixed for this instance)
#define Bb 2
#define Nn 16384
#define Mm 16384
#define Ee 49152

// ---------------- scratch (no allocations allowed) ----------------
__device__ float4   g_predP[Bb * Nn];   // (x, y, z, 0.5*|p|^2)
__device__ float4   g_tgtP [Bb * Mm];   // (x, y, z, 0.5*|t|^2)
__device__ unsigned g_rowmin[Bb * Nn];  // monotone-key encoded min over m of (0.5 t^2 - dot)
__device__ unsigned g_colmin[Bb * Mm];  // monotone-key encoded min over n of d2/2
__device__ double   g_es1[Bb];          // sum of edge lengths per batch
__device__ double   g_es2[Bb];          // sum of squared edge lengths per batch
__device__ int      g_edges_is64;       // runtime-detected edges dtype

// Monotone float<->uint key: atomicMin on key == min on float (handles negatives).
__device__ __forceinline__ unsigned f2o(float f) {
    unsigned b = __float_as_uint(f);
    return (b & 0x80000000u) ? ~b : (b ^ 0x80000000u);
}
__device__ __forceinline__ float o2f(unsigned k) {
    return __uint_as_float((k & 0x80000000u) ? (k ^ 0x80000000u) : ~k);
}

// ---------------- classify edges dtype (int32 vs int64) ----------------
// int64 edges: all values in [0, 16384) -> every odd 32-bit word (high half) is 0.
// int32 edges: odd words are uniform random in [0, 16384); 8 zeros is ~impossible.
__global__ void classify_kernel(const int* __restrict__ e32) {
    int is64 = 1;
#pragma unroll
    for (int k = 0; k < 8; k++)
        if (e32[2 * k + 1] != 0) is64 = 0;
    g_edges_is64 = is64;
}

// ---------------- prep: pack points, reset scratch ----------------
__global__ void prep_kernel(const float* __restrict__ pred, const float* __restrict__ tgt) {
    int i = blockIdx.x * blockDim.x + threadIdx.x;  // 0 .. Bb*Nn-1 (Nn == Mm)
    if (i < Bb * Nn) {
        float x = pred[3 * i], y = pred[3 * i + 1], z = pred[3 * i + 2];
        g_predP[i] = make_float4(x, y, z, 0.5f * (x * x + y * y + z * z));
        g_rowmin[i] = 0xFFFFFFFFu;
        float tx = tgt[3 * i], ty = tgt[3 * i + 1], tz = tgt[3 * i + 2];
        g_tgtP[i] = make_float4(tx, ty, tz, 0.5f * (tx * tx + ty * ty + tz * tz));
        g_colmin[i] = 0xFFFFFFFFu;
    }
    if (i < Bb) { g_es1[i] = 0.0; g_es2[i] = 0.0; }
}

// ---------------- pairwise min kernel ----------------
// Grid: (8 col-tiles, 128 row-blocks, Bb). Block: 16x16 = 256 threads.
// Block covers 128 rows x 2048 cols (16 iterations of 128 cols).
// Thread patch: 8 rows (ty) x 8 cols (tx) per iteration.
// Per pair: acc = 0.5 t^2 - p.t (3 FFMA); rowmin tracks acc (defer +0.5 p^2);
//           colmin tracks acc + 0.5 p^2 (= d2/2).
#define COLS_PER_BLOCK 2048
#define COL_ITERS 16

__global__ __launch_bounds__(256, 2) void pair_kernel() {
    __shared__ float4 sT[128];
    __shared__ float  scp[16][132];   // col partials, padded stride (528B rows, 16B-aligned)

    const int tx = threadIdx.x, ty = threadIdx.y;
    const int tid = ty * 16 + tx;
    const int b = blockIdx.z;
    const int rowBase = blockIdx.y * 128;
    const int colBase = blockIdx.x * COLS_PER_BLOCK;

    // Load this thread's 8 pred points (L2-resident)
    const float4* pp = g_predP + b * Nn + rowBase + ty * 8;
    float4 P[8];
#pragma unroll
    for (int i = 0; i < 8; i++) P[i] = pp[i];

    float rA[8];
#pragma unroll
    for (int i = 0; i < 8; i++) rA[i] = 3.4e38f;

    const float4* tp = g_tgtP + b * Mm + colBase;

    for (int it = 0; it < COL_ITERS; ++it) {
        __syncthreads();                       // protect sT/scp reuse
        if (tid < 128) sT[tid] = tp[it * 128 + tid];
        __syncthreads();

        float cA[8];
#pragma unroll
        for (int cm = 0; cm < 8; cm++) {
            const float4 T = sT[tx * 8 + cm];
            float c = 3.4e38f;
#pragma unroll
            for (int rn = 0; rn < 8; rn++) {
                float acc = fmaf(-P[rn].x, T.x, T.w);
                acc = fmaf(-P[rn].y, T.y, acc);
                acc = fmaf(-P[rn].z, T.z, acc);
                rA[rn] = fminf(rA[rn], acc);
                c = fminf(c, acc + P[rn].w);
            }
            cA[cm] = c;
        }

        // column partial reduction through smem (16 ty partials per column)
        *reinterpret_cast<float4*>(&scp[ty][tx * 8])     = make_float4(cA[0], cA[1], cA[2], cA[3]);
        *reinterpret_cast<float4*>(&scp[ty][tx * 8 + 4]) = make_float4(cA[4], cA[5], cA[6], cA[7]);
        __syncthreads();
        if (tid < 128) {
            float m = scp[0][tid];
#pragma unroll
            for (int k = 1; k < 16; k++) m = fminf(m, scp[k][tid]);
            atomicMin(&g_colmin[b * Mm + colBase + it * 128 + tid], f2o(m));
        }
    }

    // Row mins: reduce across the 16 tx lanes (within 16-lane warp halves)
#pragma unroll
    for (int o = 1; o < 16; o <<= 1) {
#pragma unroll
        for (int rn = 0; rn < 8; rn++)
            rA[rn] = fminf(rA[rn], __shfl_xor_sync(0xffffffffu, rA[rn], o));
    }
    if (tx == 0) {
#pragma unroll
        for (int rn = 0; rn < 8; rn++)
            atomicMin(&g_rowmin[b * Nn + rowBase + ty * 8 + rn], f2o(rA[rn]));
    }
}

// ---------------- edge loss partial sums ----------------
__global__ void edge_kernel(const float* __restrict__ pred, const void* __restrict__ edges) {
    const int b = blockIdx.y;
    const int is64 = g_edges_is64;
    const int*       E32 = (const int*)edges;
    const long long* E64 = (const long long*)edges;
    double s1 = 0.0, s2 = 0.0;
    for (int e = blockIdx.x * blockDim.x + threadIdx.x; e < Ee; e += gridDim.x * blockDim.x) {
        int a, c;
        if (is64) { a = (int)E64[2 * e]; c = (int)E64[2 * e + 1]; }
        else      { a = E32[2 * e];      c = E32[2 * e + 1]; }
        a &= (Nn - 1); c &= (Nn - 1);   // defensive: never OOB even if dtype guess is wrong
        const float* v1 = pred + (size_t)(b * Nn + a) * 3;
        const float* v2 = pred + (size_t)(b * Nn + c) * 3;
        float dx = v1[0] - v2[0], dy = v1[1] - v2[1], dz = v1[2] - v2[2];
        float l = sqrtf(fmaf(dx, dx, fmaf(dy, dy, dz * dz)));
        s1 += (double)l;
        s2 += (double)l * (double)l;
    }
    // warp then block reduce
    for (int o = 16; o > 0; o >>= 1) {
        s1 += __shfl_down_sync(0xffffffffu, s1, o);
        s2 += __shfl_down_sync(0xffffffffu, s2, o);
    }
    __shared__ double sh1[8], sh2[8];
    int lane = threadIdx.x & 31, w = threadIdx.x >> 5;
    if (lane == 0) { sh1[w] = s1; sh2[w] = s2; }
    __syncthreads();
    if (threadIdx.x == 0) {
        double a1 = 0.0, a2 = 0.0;
        for (int k = 0; k < (int)blockDim.x / 32; k++) { a1 += sh1[k]; a2 += sh2[k]; }
        atomicAdd(&g_es1[b], a1);
        atomicAdd(&g_es2[b], a2);
    }
}

// ---------------- finalize ----------------
__global__ void finalize_kernel(float* __restrict__ out) {
    const int t = threadIdx.x;  // 512 threads
    double sRow = 0.0, sCol = 0.0;
    for (int i = t; i < Bb * Nn; i += 512) {
        float v = o2f(g_rowmin[i]) + g_predP[i].w;      // d2/2
        sRow += (double)sqrtf(fmaxf(2.0f * v, 0.0f));
    }
    for (int i = t; i < Bb * Mm; i += 512) {
        float v = o2f(g_colmin[i]);                      // d2/2
        sCol += (double)sqrtf(fmaxf(2.0f * v, 0.0f));
    }
    for (int o = 16; o > 0; o >>= 1) {
        sRow += __shfl_down_sync(0xffffffffu, sRow, o);
        sCol += __shfl_down_sync(0xffffffffu, sCol, o);
    }
    __shared__ double shA[16], shB[16];
    int lane = t & 31, w = t >> 5;
    if (lane == 0) { shA[w] = sRow; shB[w] = sCol; }
    __syncthreads();
    if (t == 0) {
        double a = 0.0, c = 0.0;
        for (int k = 0; k < 16; k++) { a += shA[k]; c += shB[k]; }
        double c_loss = a / (double)(Bb * Nn) + c / (double)(Bb * Mm);
        double el = 0.0;
        for (int bb = 0; bb < Bb; bb++) {
            double mean = g_es1[bb] / (double)Ee;
            double var = (g_es2[bb] - (double)Ee * mean * mean) / (double)(Ee - 1);
            el += var;
        }
        el /= (double)Bb;
        double total = 1.0 * c_loss + 0.1 * el;
        out[0] = (float)total;
        out[1] = (float)c_loss;
        out[2] = (float)el;
    }
}

// ---------------- launch ----------------
extern "C" void kernel_launch(void* const* d_in, const int* in_sizes, int n_in,
                              void* d_out, int out_size) {
    const float* pred  = (const float*)d_in[0];   // (B,N,3) f32
    const float* tgt   = (const float*)d_in[1];   // (B,M,3) f32
    const void*  edges = d_in[2];                 // (E,2) int32 (JAX x64 off) or int64
    (void)in_sizes; (void)n_in; (void)out_size;

    classify_kernel<<<1, 1>>>((const int*)edges);
    prep_kernel<<<(Bb * Nn + 255) / 256, 256>>>(pred, tgt);
    pair_kernel<<<dim3(Mm / COLS_PER_BLOCK, Nn / 128, Bb), dim3(16, 16)>>>();
    edge_kernel<<<dim3(32, Bb), 256>>>(pred, edges);
    finalize_kernel<<<1, 512>>>((float*)d_out);
}

// round 10
// speedup vs baseline: 2.0280x; 2.0280x over previous
#include <cuda_runtime.h>
#include <math.h>

// Problem constants (fixed for this instance)
#define Bb 2
#define Nn 16384
#define Mm 16384
#define Ee 49152

typedef unsigned long long ull;

// ---------------- scratch (no allocations allowed) ----------------
__device__ float4   g_predP[Bb * Nn];   // (x, y, z, 0.5*|p|^2)
__device__ float4   g_tgtP [Bb * Mm];   // (x, y, z, 0.5*|t|^2)
__device__ unsigned g_rowmin[Bb * Nn];  // monotone-key encoded min over m of d2/2
__device__ unsigned g_colmin[Bb * Mm];  // monotone-key encoded min over n of d2/2
__device__ double   g_es1[Bb];          // sum of edge lengths per batch
__device__ double   g_es2[Bb];          // sum of squared edge lengths per batch
__device__ int      g_edges_is64;       // runtime-detected edges dtype

// Monotone float<->uint key: atomicMin on key == min on float (handles negatives).
__device__ __forceinline__ unsigned f2o(float f) {
    unsigned b = __float_as_uint(f);
    return (b & 0x80000000u) ? ~b : (b ^ 0x80000000u);
}
__device__ __forceinline__ float o2f(unsigned k) {
    return __uint_as_float((k & 0x80000000u) ? (k ^ 0x80000000u) : ~k);
}

// ---------------- packed f32x2 helpers (Blackwell; PTX-only forms) ----------------
__device__ __forceinline__ ull pack2(float lo, float hi) {
    ull r; asm("mov.b64 %0, {%1, %2};" : "=l"(r) : "f"(lo), "f"(hi)); return r;
}
__device__ __forceinline__ void unpack2(ull v, float& lo, float& hi) {
    asm("mov.b64 {%0, %1}, %2;" : "=f"(lo), "=f"(hi) : "l"(v));
}
__device__ __forceinline__ ull fma2(ull a, ull b, ull c) {
    ull d; asm("fma.rn.f32x2 %0, %1, %2, %3;" : "=l"(d) : "l"(a), "l"(b), "l"(c)); return d;
}
__device__ __forceinline__ ull add2(ull a, ull b) {
    ull d; asm("add.rn.f32x2 %0, %1, %2;" : "=l"(d) : "l"(a), "l"(b)); return d;
}

// ---------------- prep: pack points, reset scratch, classify edges dtype ----------------
// int64 edges: values < 16384 -> every odd 32-bit word (high half) is 0.
// int32 edges: odd words uniform in [0,16384); 8 zeros has prob ~2^-112.
__global__ void prep_kernel(const float* __restrict__ pred, const float* __restrict__ tgt,
                            const int* __restrict__ e32) {
    int i = blockIdx.x * blockDim.x + threadIdx.x;  // 0 .. Bb*Nn-1 (Nn == Mm)
    if (i < Bb * Nn) {
        float x = pred[3 * i], y = pred[3 * i + 1], z = pred[3 * i + 2];
        g_predP[i] = make_float4(x, y, z, 0.5f * (x * x + y * y + z * z));
        g_rowmin[i] = 0xFFFFFFFFu;
        float tx = tgt[3 * i], ty = tgt[3 * i + 1], tz = tgt[3 * i + 2];
        g_tgtP[i] = make_float4(tx, ty, tz, 0.5f * (tx * tx + ty * ty + tz * tz));
        g_colmin[i] = 0xFFFFFFFFu;
    }
    if (i < Bb) { g_es1[i] = 0.0; g_es2[i] = 0.0; }
    if (i == 0) {
        int is64 = 1;
#pragma unroll
        for (int k = 0; k < 8; k++)
            if (e32[2 * k + 1] != 0) is64 = 0;
        g_edges_is64 = is64;
    }
}

// ---------------- pairwise min kernel ----------------
// Grid: (8 col-tiles, 128 row-blocks, Bb). Block: 16x16 = 256 threads.
// Block covers 128 rows x 2048 cols (16 iterations of 128 cols).
// Thread patch per iter: 8 rows x 8 cols; cols owned as 4 f32x2 pairs at
// pair index cm*16+tx (interleaved -> conflict-free LDS.128).
// T staged SoA-by-pair: sTxy[p]=(x0,x1,y0,y1), sTzw[p]=(z0,z1,w0,w1), w=0.5|t|^2.
// Per 2 pairs: v2 = (Tw2+Pw2) - p.t  via 1 ADD2 + 3 FMA2 (P pre-negated),
// then 4 FMNMX (2 rowmin, 2 colmin). v = d2/2 exactly (both mins carry it).
#define COLS_PER_BLOCK 2048
#define COL_ITERS 16

__global__ __launch_bounds__(256, 2) void pair_kernel() {
    __shared__ ulonglong2 sTxy[64];
    __shared__ ulonglong2 sTzw[64];
    __shared__ float      scp[16][132];   // col partials, padded stride

    const int tx = threadIdx.x, ty = threadIdx.y;
    const int tid = ty * 16 + tx;
    const int b = blockIdx.z;
    const int rowBase = blockIdx.y * 128;
    const int colBase = blockIdx.x * COLS_PER_BLOCK;

    // Load this thread's 8 pred points (L2-resident) and pre-pack (negated xyz).
    const float4* pp = g_predP + b * Nn + rowBase + ty * 8;
    ull Px2[8], Py2[8], Pz2[8], Pw2[8];
#pragma unroll
    for (int i = 0; i < 8; i++) {
        float4 P = pp[i];
        Px2[i] = pack2(-P.x, -P.x);
        Py2[i] = pack2(-P.y, -P.y);
        Pz2[i] = pack2(-P.z, -P.z);
        Pw2[i] = pack2( P.w,  P.w);
    }

    float rA[8];
#pragma unroll
    for (int i = 0; i < 8; i++) rA[i] = 3.4e38f;

    const float4* tp = g_tgtP + b * Mm + colBase;

    for (int it = 0; it < COL_ITERS; ++it) {
        __syncthreads();                       // protect sT/scp reuse
        if (tid < 128) {
            float4 T = tp[it * 128 + tid];
            int p = tid >> 1, h = tid & 1;
            float* fxy = (float*)&sTxy[p];
            float* fzw = (float*)&sTzw[p];
            fxy[h] = T.x; fxy[2 + h] = T.y;
            fzw[h] = T.z; fzw[2 + h] = T.w;
        }
        __syncthreads();

        float cLo[4], cHi[4];
#pragma unroll
        for (int cm = 0; cm < 4; cm++) {
            const ulonglong2 txy = sTxy[cm * 16 + tx];  // (x0,x1 | y0,y1)
            const ulonglong2 tzw = sTzw[cm * 16 + tx];  // (z0,z1 | w0,w1)
            float lo0, hi0;
            {
                ull acc = add2(tzw.y, Pw2[0]);
                acc = fma2(Pz2[0], tzw.x, acc);
                acc = fma2(Py2[0], txy.y, acc);
                acc = fma2(Px2[0], txy.x, acc);
                unpack2(acc, lo0, hi0);
                rA[0] = fminf(rA[0], fminf(lo0, hi0));
            }
            float cl = lo0, ch = hi0;
#pragma unroll
            for (int rn = 1; rn < 8; rn++) {
                ull acc = add2(tzw.y, Pw2[rn]);
                acc = fma2(Pz2[rn], tzw.x, acc);
                acc = fma2(Py2[rn], txy.y, acc);
                acc = fma2(Px2[rn], txy.x, acc);
                float lo, hi; unpack2(acc, lo, hi);
                rA[rn] = fminf(rA[rn], fminf(lo, hi));
                cl = fminf(cl, lo);
                ch = fminf(ch, hi);
            }
            cLo[cm] = cl; cHi[cm] = ch;
        }

        // column partial write: thread owns cols 32*cm + 2*tx (+1)
#pragma unroll
        for (int cm = 0; cm < 4; cm++) {
            float2* dst = (float2*)&scp[ty][32 * cm + 2 * tx];
            *dst = make_float2(cLo[cm], cHi[cm]);
        }
        __syncthreads();
        if (tid < 128) {
            float m = scp[0][tid];
#pragma unroll
            for (int k = 1; k < 16; k++) m = fminf(m, scp[k][tid]);
            atomicMin(&g_colmin[b * Mm + colBase + it * 128 + tid], f2o(m));
        }
    }

    // Row mins: reduce across the 16 tx lanes (within 16-lane warp halves)
#pragma unroll
    for (int o = 1; o < 16; o <<= 1) {
#pragma unroll
        for (int rn = 0; rn < 8; rn++)
            rA[rn] = fminf(rA[rn], __shfl_xor_sync(0xffffffffu, rA[rn], o));
    }
    if (tx == 0) {
#pragma unroll
        for (int rn = 0; rn < 8; rn++)
            atomicMin(&g_rowmin[b * Nn + rowBase + ty * 8 + rn], f2o(rA[rn]));
    }
}

// ---------------- edge loss partial sums ----------------
__global__ void edge_kernel(const float* __restrict__ pred, const void* __restrict__ edges) {
    const int b = blockIdx.y;
    const int is64 = g_edges_is64;
    const int*       E32 = (const int*)edges;
    const long long* E64 = (const long long*)edges;
    double s1 = 0.0, s2 = 0.0;
    for (int e = blockIdx.x * blockDim.x + threadIdx.x; e < Ee; e += gridDim.x * blockDim.x) {
        int a, c;
        if (is64) { a = (int)E64[2 * e]; c = (int)E64[2 * e + 1]; }
        else      { a = E32[2 * e];      c = E32[2 * e + 1]; }
        a &= (Nn - 1); c &= (Nn - 1);   // defensive: never OOB even if dtype guess is wrong
        const float* v1 = pred + (size_t)(b * Nn + a) * 3;
        const float* v2 = pred + (size_t)(b * Nn + c) * 3;
        float dx = v1[0] - v2[0], dy = v1[1] - v2[1], dz = v1[2] - v2[2];
        float l = sqrtf(fmaf(dx, dx, fmaf(dy, dy, dz * dz)));
        s1 += (double)l;
        s2 += (double)l * (double)l;
    }
    // warp then block reduce
    for (int o = 16; o > 0; o >>= 1) {
        s1 += __shfl_down_sync(0xffffffffu, s1, o);
        s2 += __shfl_down_sync(0xffffffffu, s2, o);
    }
    __shared__ double sh1[8], sh2[8];
    int lane = threadIdx.x & 31, w = threadIdx.x >> 5;
    if (lane == 0) { sh1[w] = s1; sh2[w] = s2; }
    __syncthreads();
    if (threadIdx.x == 0) {
        double a1 = 0.0, a2 = 0.0;
        for (int k = 0; k < (int)blockDim.x / 32; k++) { a1 += sh1[k]; a2 += sh2[k]; }
        atomicAdd(&g_es1[b], a1);
        atomicAdd(&g_es2[b], a2);
    }
}

// ---------------- finalize ----------------
__global__ void finalize_kernel(float* __restrict__ out) {
    const int t = threadIdx.x;  // 512 threads
    double sRow = 0.0, sCol = 0.0;
    for (int i = t; i < Bb * Nn; i += 512) {
        float v = o2f(g_rowmin[i]);                      // full d2/2 now
        sRow += (double)sqrtf(fmaxf(2.0f * v, 0.0f));
    }
    for (int i = t; i < Bb * Mm; i += 512) {
        float v = o2f(g_colmin[i]);                      // d2/2
        sCol += (double)sqrtf(fmaxf(2.0f * v, 0.0f));
    }
    for (int o = 16; o > 0; o >>= 1) {
        sRow += __shfl_down_sync(0xffffffffu, sRow, o);
        sCol += __shfl_down_sync(0xffffffffu, sCol, o);
    }
    __shared__ double shA[16], shB[16];
    int lane = t & 31, w = t >> 5;
    if (lane == 0) { shA[w] = sRow; shB[w] = sCol; }
    __syncthreads();
    if (t == 0) {
        double a = 0.0, c = 0.0;
        for (int k = 0; k < 16; k++) { a += shA[k]; c += shB[k]; }
        double c_loss = a / (double)(Bb * Nn) + c / (double)(Bb * Mm);
        double el = 0.0;
        for (int bb = 0; bb < Bb; bb++) {
            double mean = g_es1[bb] / (double)Ee;
            double var = (g_es2[bb] - (double)Ee * mean * mean) / (double)(Ee - 1);
            el += var;
        }
        el /= (double)Bb;
        double total = 1.0 * c_loss + 0.1 * el;
        out[0] = (float)total;
        out[1] = (float)c_loss;
        out[2] = (float)el;
    }
}

// ---------------- launch ----------------
extern "C" void kernel_launch(void* const* d_in, const int* in_sizes, int n_in,
                              void* d_out, int out_size) {
    const float* pred  = (const float*)d_in[0];   // (B,N,3) f32
    const float* tgt   = (const float*)d_in[1];   // (B,M,3) f32
    const void*  edges = d_in[2];                 // (E,2) int32 (JAX x64 off) or int64
    (void)in_sizes; (void)n_in; (void)out_size;

    prep_kernel<<<(Bb * Nn + 255) / 256, 256>>>(pred, tgt, (const int*)edges);
    pair_kernel<<<dim3(Mm / COLS_PER_BLOCK, Nn / 128, Bb), dim3(16, 16)>>>();
    edge_kernel<<<dim3(96, Bb), 256>>>(pred, edges);
    finalize_kernel<<<1, 512>>>((float*)d_out);
}

// round 11
// speedup vs baseline: 2.7048x; 1.3337x over previous
#include <cuda_runtime.h>
#include <math.h>

// Problem constants (fixed for this instance)
#define Bb 2
#define Nn 16384
#define Mm 16384
#define Ee 49152

typedef unsigned long long ull;

// ---------------- scratch (no allocations allowed) ----------------
__device__ float4   g_predP[Bb * Nn];   // (x, y, z, 0.5*|p|^2)
__device__ float4   g_tgtP [Bb * Mm];   // (x, y, z, 0.5*|t|^2)
__device__ unsigned g_rowmin[Bb * Nn];  // monotone-key encoded min over m of d2/2
__device__ unsigned g_colmin[Bb * Mm];  // monotone-key encoded min over n of d2/2
__device__ double   g_es1[Bb];          // sum of edge lengths per batch
__device__ double   g_es2[Bb];          // sum of squared edge lengths per batch
__device__ double   g_sumRow;           // sum over all (b,n) of min-dist
__device__ double   g_sumCol;           // sum over all (b,m) of min-dist
__device__ int      g_edges_is64;       // runtime-detected edges dtype

// Monotone float<->uint key: atomicMin on key == min on float (handles negatives).
__device__ __forceinline__ unsigned f2o(float f) {
    unsigned b = __float_as_uint(f);
    return (b & 0x80000000u) ? ~b : (b ^ 0x80000000u);
}
__device__ __forceinline__ float o2f(unsigned k) {
    return __uint_as_float((k & 0x80000000u) ? (k ^ 0x80000000u) : ~k);
}

// ---------------- packed f32x2 helpers (Blackwell; PTX-only forms) ----------------
__device__ __forceinline__ ull pack2(float lo, float hi) {
    ull r; asm("mov.b64 %0, {%1, %2};" : "=l"(r) : "f"(lo), "f"(hi)); return r;
}
__device__ __forceinline__ void unpack2(ull v, float& lo, float& hi) {
    asm("mov.b64 {%0, %1}, %2;" : "=f"(lo), "=f"(hi) : "l"(v));
}
__device__ __forceinline__ ull fma2(ull a, ull b, ull c) {
    ull d; asm("fma.rn.f32x2 %0, %1, %2, %3;" : "=l"(d) : "l"(a), "l"(b), "l"(c)); return d;
}
__device__ __forceinline__ ull add2(ull a, ull b) {
    ull d; asm("add.rn.f32x2 %0, %1, %2;" : "=l"(d) : "l"(a), "l"(b)); return d;
}

// ---------------- prep: pack points, reset scratch, classify edges dtype ----------------
// int64 edges: values < 16384 -> every odd 32-bit word (high half) is 0.
// int32 edges: odd words uniform in [0,16384); 8 zeros has prob ~2^-112.
__global__ void prep_kernel(const float* __restrict__ pred, const float* __restrict__ tgt,
                            const int* __restrict__ e32) {
    int i = blockIdx.x * blockDim.x + threadIdx.x;  // 0 .. Bb*Nn-1 (Nn == Mm)
    if (i < Bb * Nn) {
        float x = pred[3 * i], y = pred[3 * i + 1], z = pred[3 * i + 2];
        g_predP[i] = make_float4(x, y, z, 0.5f * (x * x + y * y + z * z));
        g_rowmin[i] = 0xFFFFFFFFu;
        float tx = tgt[3 * i], ty = tgt[3 * i + 1], tz = tgt[3 * i + 2];
        g_tgtP[i] = make_float4(tx, ty, tz, 0.5f * (tx * tx + ty * ty + tz * tz));
        g_colmin[i] = 0xFFFFFFFFu;
    }
    if (i < Bb) { g_es1[i] = 0.0; g_es2[i] = 0.0; }
    if (i == 0) {
        g_sumRow = 0.0; g_sumCol = 0.0;
        int is64 = 1;
#pragma unroll
        for (int k = 0; k < 8; k++)
            if (e32[2 * k + 1] != 0) is64 = 0;
        g_edges_is64 = is64;
    }
}

// ---------------- pairwise min kernel ----------------
// Grid: (8 col-tiles, 128 row-blocks, Bb). Block: 16x16 = 256 threads.
// Block covers 128 rows x 2048 cols (16 iterations of 128 cols).
// Thread patch per iter: 8 rows x 8 cols; cols owned as 4 f32x2 pairs at
// pair index cm*16+tx (interleaved -> conflict-free LDS.128).
// T staged SoA-by-pair: sTxy[p]=(x0,x1,y0,y1), sTzw[p]=(z0,z1,w0,w1), w=0.5|t|^2.
// Per 2 pairs: v2 = (Tw2+Pw2) - p.t  via 1 ADD2 + 3 FMA2 (P pre-negated),
// then 4 FMNMX (2 rowmin, 2 colmin). v = d2/2 exactly (both mins carry it).
#define COLS_PER_BLOCK 2048
#define COL_ITERS 16

__global__ __launch_bounds__(256, 2) void pair_kernel() {
    __shared__ ulonglong2 sTxy[64];
    __shared__ ulonglong2 sTzw[64];
    __shared__ float      scp[16][132];   // col partials, padded stride

    const int tx = threadIdx.x, ty = threadIdx.y;
    const int tid = ty * 16 + tx;
    const int b = blockIdx.z;
    const int rowBase = blockIdx.y * 128;
    const int colBase = blockIdx.x * COLS_PER_BLOCK;

    // Load this thread's 8 pred points (L2-resident) and pre-pack (negated xyz).
    const float4* pp = g_predP + b * Nn + rowBase + ty * 8;
    ull Px2[8], Py2[8], Pz2[8], Pw2[8];
#pragma unroll
    for (int i = 0; i < 8; i++) {
        float4 P = pp[i];
        Px2[i] = pack2(-P.x, -P.x);
        Py2[i] = pack2(-P.y, -P.y);
        Pz2[i] = pack2(-P.z, -P.z);
        Pw2[i] = pack2( P.w,  P.w);
    }

    float rA[8];
#pragma unroll
    for (int i = 0; i < 8; i++) rA[i] = 3.4e38f;

    const float4* tp = g_tgtP + b * Mm + colBase;

    for (int it = 0; it < COL_ITERS; ++it) {
        __syncthreads();                       // protect sT/scp reuse
        if (tid < 128) {
            float4 T = tp[it * 128 + tid];
            int p = tid >> 1, h = tid & 1;
            float* fxy = (float*)&sTxy[p];
            float* fzw = (float*)&sTzw[p];
            fxy[h] = T.x; fxy[2 + h] = T.y;
            fzw[h] = T.z; fzw[2 + h] = T.w;
        }
        __syncthreads();

        float cLo[4], cHi[4];
#pragma unroll
        for (int cm = 0; cm < 4; cm++) {
            const ulonglong2 txy = sTxy[cm * 16 + tx];  // (x0,x1 | y0,y1)
            const ulonglong2 tzw = sTzw[cm * 16 + tx];  // (z0,z1 | w0,w1)
            float lo0, hi0;
            {
                ull acc = add2(tzw.y, Pw2[0]);
                acc = fma2(Pz2[0], tzw.x, acc);
                acc = fma2(Py2[0], txy.y, acc);
                acc = fma2(Px2[0], txy.x, acc);
                unpack2(acc, lo0, hi0);
                rA[0] = fminf(rA[0], fminf(lo0, hi0));
            }
            float cl = lo0, ch = hi0;
#pragma unroll
            for (int rn = 1; rn < 8; rn++) {
                ull acc = add2(tzw.y, Pw2[rn]);
                acc = fma2(Pz2[rn], tzw.x, acc);
                acc = fma2(Py2[rn], txy.y, acc);
                acc = fma2(Px2[rn], txy.x, acc);
                float lo, hi; unpack2(acc, lo, hi);
                rA[rn] = fminf(rA[rn], fminf(lo, hi));
                cl = fminf(cl, lo);
                ch = fminf(ch, hi);
            }
            cLo[cm] = cl; cHi[cm] = ch;
        }

        // column partial write: thread owns cols 32*cm + 2*tx (+1)
#pragma unroll
        for (int cm = 0; cm < 4; cm++) {
            float2* dst = (float2*)&scp[ty][32 * cm + 2 * tx];
            *dst = make_float2(cLo[cm], cHi[cm]);
        }
        __syncthreads();
        if (tid < 128) {
            float m = scp[0][tid];
#pragma unroll
            for (int k = 1; k < 16; k++) m = fminf(m, scp[k][tid]);
            atomicMin(&g_colmin[b * Mm + colBase + it * 128 + tid], f2o(m));
        }
    }

    // Row mins: reduce across the 16 tx lanes (within 16-lane warp halves)
#pragma unroll
    for (int o = 1; o < 16; o <<= 1) {
#pragma unroll
        for (int rn = 0; rn < 8; rn++)
            rA[rn] = fminf(rA[rn], __shfl_xor_sync(0xffffffffu, rA[rn], o));
    }
    if (tx == 0) {
#pragma unroll
        for (int rn = 0; rn < 8; rn++)
            atomicMin(&g_rowmin[b * Nn + rowBase + ty * 8 + rn], f2o(rA[rn]));
    }
}

// ---------------- edge loss partial sums ----------------
__global__ void edge_kernel(const float* __restrict__ pred, const void* __restrict__ edges) {
    const int b = blockIdx.y;
    const int is64 = g_edges_is64;
    const int*       E32 = (const int*)edges;
    const long long* E64 = (const long long*)edges;
    double s1 = 0.0, s2 = 0.0;
    for (int e = blockIdx.x * blockDim.x + threadIdx.x; e < Ee; e += gridDim.x * blockDim.x) {
        int a, c;
        if (is64) { a = (int)E64[2 * e]; c = (int)E64[2 * e + 1]; }
        else      { a = E32[2 * e];      c = E32[2 * e + 1]; }
        a &= (Nn - 1); c &= (Nn - 1);   // defensive: never OOB even if dtype guess is wrong
        const float* v1 = pred + (size_t)(b * Nn + a) * 3;
        const float* v2 = pred + (size_t)(b * Nn + c) * 3;
        float dx = v1[0] - v2[0], dy = v1[1] - v2[1], dz = v1[2] - v2[2];
        float l = sqrtf(fmaf(dx, dx, fmaf(dy, dy, dz * dz)));
        s1 += (double)l;
        s2 += (double)l * (double)l;
    }
    // warp then block reduce
    for (int o = 16; o > 0; o >>= 1) {
        s1 += __shfl_down_sync(0xffffffffu, s1, o);
        s2 += __shfl_down_sync(0xffffffffu, s2, o);
    }
    __shared__ double sh1[8], sh2[8];
    int lane = threadIdx.x & 31, w = threadIdx.x >> 5;
    if (lane == 0) { sh1[w] = s1; sh2[w] = s2; }
    __syncthreads();
    if (threadIdx.x == 0) {
        double a1 = 0.0, a2 = 0.0;
        for (int k = 0; k < (int)blockDim.x / 32; k++) { a1 += sh1[k]; a2 += sh2[k]; }
        atomicAdd(&g_es1[b], a1);
        atomicAdd(&g_es2[b], a2);
    }
}

// ---------------- grid-wide min-array reduction (replaces single-block finalize) ----------------
// 128 blocks x 256 threads; each element of rowmin/colmin touched exactly once.
__global__ void reduce_kernel() {
    const int tid = blockIdx.x * blockDim.x + threadIdx.x;
    const int stride = gridDim.x * blockDim.x;
    double sRow = 0.0, sCol = 0.0;
    for (int i = tid; i < Bb * Nn; i += stride) {
        float vr = o2f(g_rowmin[i]);
        float vc = o2f(g_colmin[i]);
        sRow += (double)sqrtf(fmaxf(2.0f * vr, 0.0f));
        sCol += (double)sqrtf(fmaxf(2.0f * vc, 0.0f));
    }
    for (int o = 16; o > 0; o >>= 1) {
        sRow += __shfl_down_sync(0xffffffffu, sRow, o);
        sCol += __shfl_down_sync(0xffffffffu, sCol, o);
    }
    __shared__ double shA[8], shB[8];
    int lane = threadIdx.x & 31, w = threadIdx.x >> 5;
    if (lane == 0) { shA[w] = sRow; shB[w] = sCol; }
    __syncthreads();
    if (threadIdx.x == 0) {
        double a = 0.0, c = 0.0;
#pragma unroll
        for (int k = 0; k < 8; k++) { a += shA[k]; c += shB[k]; }
        atomicAdd(&g_sumRow, a);
        atomicAdd(&g_sumCol, c);
    }
}

// ---------------- final scalar combine ----------------
__global__ void final_kernel(float* __restrict__ out) {
    if (threadIdx.x != 0) return;
    double c_loss = g_sumRow / (double)(Bb * Nn) + g_sumCol / (double)(Bb * Mm);
    double el = 0.0;
    for (int bb = 0; bb < Bb; bb++) {
        double mean = g_es1[bb] / (double)Ee;
        double var = (g_es2[bb] - (double)Ee * mean * mean) / (double)(Ee - 1);
        el += var;
    }
    el /= (double)Bb;
    double total = 1.0 * c_loss + 0.1 * el;
    out[0] = (float)total;
    out[1] = (float)c_loss;
    out[2] = (float)el;
}

// ---------------- launch ----------------
extern "C" void kernel_launch(void* const* d_in, const int* in_sizes, int n_in,
                              void* d_out, int out_size) {
    const float* pred  = (const float*)d_in[0];   // (B,N,3) f32
    const float* tgt   = (const float*)d_in[1];   // (B,M,3) f32
    const void*  edges = d_in[2];                 // (E,2) int32 (JAX x64 off) or int64
    (void)in_sizes; (void)n_in; (void)out_size;

    prep_kernel<<<(Bb * Nn + 255) / 256, 256>>>(pred, tgt, (const int*)edges);
    pair_kernel<<<dim3(Mm / COLS_PER_BLOCK, Nn / 128, Bb), dim3(16, 16)>>>();
    edge_kernel<<<dim3(96, Bb), 256>>>(pred, edges);
    reduce_kernel<<<128, 256>>>();
    final_kernel<<<1, 32>>>((float*)d_out);
}